// round 8
// baseline (speedup 1.0000x reference)
#include <cuda_runtime.h>
#include <math.h>

#define KCODES 512
#define DDIM   64
#define HDIM   64
#define LN_EPS 1e-5f

#define NVB    64      // dist blocks
#define VPB    8       // token-values per dist block
#define CCHUNK 128     // codes per smem chunk
#define NCH    4       // 512 / 128

// device scratch / LUTs (zero-initialized at module load)
__device__ float4 g_q_lut4[KCODES * 16];      // chosen codebook row per v (float4 view)
__device__ float  g_idx_f[KCODES];            // argmin index per v, as float
__device__ double g_err_lut[KCODES];          // ||cb[idx]-z_v||^2
__device__ int    g_cnt[KCODES];              // histogram of t (reset by scatter)
__device__ int    g_ticket;                   // loss ticket

// ---------------------------------------------------------------------------
// Kernel 1: fully self-contained per block. 64 blocks x 512 threads.
// Block b owns values v in [8b, 8b+8): histogram slice, encoder, distances to
// ALL 512 codes (4 smem chunks of 128), in-block argmin, LUT fill. Last block
// (single global ticket) computes the loss.
// All fp32 accumulations: single accumulator, sequential ascending order,
// strict-< ascending-k argmin — identical to all previous passing rounds.
// ---------------------------------------------------------------------------
__global__ __launch_bounds__(512, 1)
void dist_kernel(const float* __restrict__ W1,
                 const float* __restrict__ b1,
                 const float* __restrict__ lng,
                 const float* __restrict__ lnb,
                 const float* __restrict__ W2,
                 const float* __restrict__ b2,
                 const float* __restrict__ cb,
                 const int*   __restrict__ t,
                 float*       __restrict__ loss_out,
                 int n) {
    __shared__ float  h_sh[VPB * 65];
    __shared__ float  z_sh[VPB * 65];
    __shared__ float4 cb_sh4[CCHUNK * 17];     // padded stride 17 float4 (34 KB)
    __shared__ float  s_mu[VPB], s_rs[VPB], s_z2[VPB];
    __shared__ float  s_e2[CCHUNK];
    __shared__ float  s_pd[VPB * 64];
    __shared__ int    s_pi[VPB * 64];
    __shared__ int    s_bestv[VPB];
    __shared__ int    sc[KCODES];
    __shared__ int    s_glast;
    __shared__ double dacc[512];

    const int tid = threadIdx.x;               // 0..511
    const int v0  = blockIdx.x * VPB;

    // ---- private histogram of this block's 1/64 slice of t ----
    sc[tid] = 0;
    __syncthreads();
    {
        const int nq = n >> 2;                 // n divisible by 4
        const int4* t4 = reinterpret_cast<const int4*>(t);
        for (int j = blockIdx.x * 512 + tid; j < nq; j += NVB * 512) {
            const int4 vv = __ldg(&t4[j]);
            atomicAdd(&sc[vv.x], 1);
            atomicAdd(&sc[vv.y], 1);
            atomicAdd(&sc[vv.z], 1);
            atomicAdd(&sc[vv.w], 1);
        }
    }

    // ---- h = norm*W1 + b1 : exactly one item per thread ----
    {
        const int vl = tid >> 6, j = tid & 63;
        const float norm = ((float)(v0 + vl) / (float)(KCODES - 1)) * 2.0f - 1.0f;
        h_sh[vl * 65 + j] = norm * W1[j] + b1[j];
    }
    __syncthreads();

    // flush private histogram to global (sc complete after the sync above)
    {
        const int c = sc[tid];
        if (c) atomicAdd(&g_cnt[tid], c);
    }

    // ---- LN stats (sequential ascending j, one v per thread) ----
    if (tid < VPB) {
        float s = 0.0f;
        for (int j = 0; j < HDIM; j++) s += h_sh[tid * 65 + j];
        const float mu = s / (float)HDIM;
        float vs = 0.0f;
        for (int j = 0; j < HDIM; j++) {
            const float d = h_sh[tid * 65 + j] - mu;
            vs += d * d;
        }
        s_mu[tid] = mu;
        s_rs[tid] = 1.0f / sqrtf(vs / (float)HDIM + LN_EPS);
    }
    __syncthreads();

    // ---- LN + relu (one item per thread) ----
    {
        const int vl = tid >> 6, j = tid & 63;
        float x = (h_sh[vl * 65 + j] - s_mu[vl]) * s_rs[vl] * lng[j] + lnb[j];
        h_sh[vl * 65 + j] = fmaxf(x, 0.0f);
    }
    __syncthreads();

    // ---- z = h @ W2 + b2 (sequential ascending j, one item per thread) ----
    {
        const int vl = tid >> 6, d = tid & 63;
        float acc = 0.0f;
        for (int j = 0; j < HDIM; j++)
            acc += h_sh[vl * 65 + j] * __ldg(&W2[j * DDIM + d]);
        z_sh[vl * 65 + d] = acc + b2[d];
    }
    __syncthreads();

    // ---- z2 (sequential ascending d) ----
    if (tid < VPB) {
        float s = 0.0f;
        for (int d = 0; d < DDIM; d++) {
            const float zz = z_sh[tid * 65 + d];
            s += zz * zz;
        }
        s_z2[tid] = s;
    }
    __syncthreads();

    // ---- distance sweep over 4 chunks of 128 codes ----
    const int vl = tid & 7;                    // value within block
    const int kg = tid >> 3;                   // code-pair group 0..63
    const float* zrow = &z_sh[vl * 65];

    float bd = INFINITY;
    int   bi = 0;

    for (int c = 0; c < NCH; c++) {
        // stage 128 codes, padded stride 17 float4 (conflict-free reads)
        {
            const float4* src = reinterpret_cast<const float4*>(
                cb + (size_t)(c * CCHUNK) * DDIM);
            for (int j = tid; j < CCHUNK * 16; j += 512)
                cb_sh4[(j >> 4) * 17 + (j & 15)] = src[j];
        }
        // e2 per code from global (float4 xyzw = ascending d, same as before)
        if (tid < CCHUNK) {
            const float4* e = reinterpret_cast<const float4*>(
                cb + (size_t)(c * CCHUNK + tid) * DDIM);
            float acc = 0.0f;
            #pragma unroll
            for (int i = 0; i < 16; i++) {
                const float4 cc = e[i];
                acc += cc.x * cc.x;
                acc += cc.y * cc.y;
                acc += cc.z * cc.z;
                acc += cc.w * cc.w;
            }
            s_e2[tid] = acc;
        }
        __syncthreads();

        // each thread: 2 contiguous codes (ascending k within and across chunks)
        const int kl0 = kg * 2;
        const float4* e0 = &cb_sh4[kl0 * 17];
        const float4* e1 = &cb_sh4[(kl0 + 1) * 17];
        float dot0 = 0.0f, dot1 = 0.0f;
        #pragma unroll
        for (int i = 0; i < 16; i++) {
            const float4 a = e0[i];
            const float4 b = e1[i];
            const float z0 = zrow[4 * i + 0];
            const float z1 = zrow[4 * i + 1];
            const float z2r = zrow[4 * i + 2];
            const float z3 = zrow[4 * i + 3];
            dot0 += z0 * a.x; dot0 += z1 * a.y; dot0 += z2r * a.z; dot0 += z3 * a.w;
            dot1 += z0 * b.x; dot1 += z1 * b.y; dot1 += z2r * b.z; dot1 += z3 * b.w;
        }
        const float zz2 = s_z2[vl];
        const float d0 = zz2 - 2.0f * dot0 + s_e2[kl0];
        const float d1 = zz2 - 2.0f * dot1 + s_e2[kl0 + 1];
        const int   k  = c * CCHUNK + kl0;
        if (d0 < bd) { bd = d0; bi = k; }
        if (d1 < bd) { bd = d1; bi = k + 1; }
        __syncthreads();                       // protect cb_sh4 before reload
    }

    s_pd[vl * 64 + kg] = bd;
    s_pi[vl * 64 + kg] = bi;
    __syncthreads();

    // ---- in-block argmin combine (ascending kg), err, idx ----
    if (tid < VPB) {
        const int v = v0 + tid;
        float bdv = INFINITY;
        int   biv = 0;
        for (int g = 0; g < 64; g++) {
            const float d2 = s_pd[tid * 64 + g];
            if (d2 < bdv) { bdv = d2; biv = s_pi[tid * 64 + g]; }
        }
        s_bestv[tid] = biv;
        g_idx_f[v]   = (float)biv;

        const float* e  = cb + (size_t)biv * DDIM;
        const float* zp = &z_sh[tid * 65];
        double a0 = 0.0, a1 = 0.0, a2 = 0.0, a3 = 0.0;
        for (int d = 0; d < DDIM; d += 4) {
            const double f0 = (double)e[d + 0] - (double)zp[d + 0];
            const double f1 = (double)e[d + 1] - (double)zp[d + 1];
            const double f2 = (double)e[d + 2] - (double)zp[d + 2];
            const double f3 = (double)e[d + 3] - (double)zp[d + 3];
            a0 += f0 * f0; a1 += f1 * f1; a2 += f2 * f2; a3 += f3 * f3;
        }
        g_err_lut[v] = (a0 + a1) + (a2 + a3);
    }
    __syncthreads();

    // ---- fill q LUT (one float per thread) ----
    {
        const int vl2 = tid >> 6, d = tid & 63;
        float* q_lut = reinterpret_cast<float*>(g_q_lut4);
        q_lut[(v0 + vl2) * DDIM + d] = cb[(size_t)s_bestv[vl2] * DDIM + d];
    }

    // ---- single global ticket: last block computes the loss ----
    __threadfence();
    if (tid == 0) {
        const int gt = atomicAdd(&g_ticket, 1);
        s_glast = (gt == NVB - 1) ? 1 : 0;
    }
    __syncthreads();
    if (!s_glast) return;
    __threadfence();
    if (tid == 0) g_ticket = 0;                // clean for next graph replay
    if (loss_out == nullptr) return;

    dacc[tid] = (double)g_cnt[tid] * g_err_lut[tid];
    __syncthreads();
    for (int off = 256; off > 0; off >>= 1) {
        if (tid < off) dacc[tid] += dacc[tid + off];
        __syncthreads();
    }
    if (tid == 0) {
        loss_out[0] = (float)(1.25 * dacc[0] / ((double)n * (double)DDIM));
    }
}

// ---------------------------------------------------------------------------
// Kernel 2: pure scatter — unchanged from the measured-17.7us round-7 version.
// Block 0 resets g_cnt for the next graph replay.
// ---------------------------------------------------------------------------
#define SC_UNROLL 4
__global__ void scatter_kernel(const int* __restrict__ t,
                               float4* __restrict__ q_out,
                               float* __restrict__ idx_out, int n) {
    if (blockIdx.x == 0) {                     // reset hist for next replay
        g_cnt[threadIdx.x] = 0;
        g_cnt[threadIdx.x + 256] = 0;
    }
    const int total  = n * 16;
    const int stride = gridDim.x * blockDim.x;
    const int i0     = blockIdx.x * blockDim.x + threadIdx.x;

    int    v[SC_UNROLL];
    float4 val[SC_UNROLL];

    #pragma unroll
    for (int j = 0; j < SC_UNROLL; j++) {
        const int i = i0 + j * stride;
        if (i < total) {
            v[j]   = __ldg(t + (i >> 4));
            val[j] = g_q_lut4[(v[j] << 4) + (i & 15)];
        } else {
            v[j] = -1;
        }
    }

    #pragma unroll
    for (int j = 0; j < SC_UNROLL; j++) {
        const int i = i0 + j * stride;
        if (v[j] >= 0) {
            q_out[i] = val[j];
            if ((i & 15) == 0 && idx_out != nullptr) {
                idx_out[i >> 4] = g_idx_f[v[j]];
            }
        }
    }
}

// ---------------------------------------------------------------------------
extern "C" void kernel_launch(void* const* d_in, const int* in_sizes, int n_in,
                              void* d_out, int out_size) {
    const int*   t    = (const int*)d_in[0];
    const float* W1   = (const float*)d_in[1];
    const float* b1   = (const float*)d_in[2];
    const float* lng  = (const float*)d_in[3];
    const float* lnb  = (const float*)d_in[4];
    const float* W2   = (const float*)d_in[5];
    const float* b2   = (const float*)d_in[6];
    const float* cb   = (const float*)d_in[7];

    const int n = in_sizes[0];                 // N = B*T = 262144 tokens
    float* out = (float*)d_out;

    // Output layout: [ q : n*64 floats | idx : n floats | loss : 1 float ]
    const bool full = (out_size >= n * DDIM + n + 1);
    float* q_out    = out;
    float* idx_out  = full ? (out + (size_t)n * DDIM) : nullptr;
    float* loss_out = full ? (out + (size_t)n * DDIM + n) : nullptr;

    dist_kernel<<<NVB, 512>>>(W1, b1, lng, lnb, W2, b2, cb, t, loss_out, n);

    const int total   = n * 16;
    const int threads = 256;
    const int blocks  = (total + threads * SC_UNROLL - 1) / (threads * SC_UNROLL);
    scatter_kernel<<<blocks, threads>>>(t, (float4*)q_out, idx_out, n);
}